// round 9
// baseline (speedup 1.0000x reference)
#include <cuda_runtime.h>

// TpsGridGen: theta (64, 50) -> grid (64, 256, 192, 2) fp32
// Fused scalar kernel (tcgen05 unavailable through compute_103 lowering).
// R9: batch-QUARTER split (16 batches/block) -> 3072 warps for issue coverage.
//     U packed as (px0,px1) f32x2 pairs (56 regs, not duplicated);
//     coefs stored axis-duplicated (cx,cx,cy,cy) in smem, broadcast LDS.128.
//     fma.rn.f32x2 throughout; fma-pipe floor ~5.2us is the target.

#define OUT_H 256
#define OUT_W 192
#define NCP   25
#define NCOEF 28   // 25 RBF + [1, gx, gy] affine
#define NBQ   16   // batches per block (quarter)

// Control-point coords: P_X[k] = ax[k/5], P_Y[k] = ax[k%5], ax = linspace(-1,1,5)
__host__ __device__ constexpr float cpx(int n) { return 0.5f * (float)(n / 5) - 1.0f; }
__host__ __device__ constexpr float cpy(int n) { return 0.5f * (float)(n % 5) - 1.0f; }

// ---------------------------------------------------------------------------
// Compile-time inv(L) (constexpr fp64 Gauss-Jordan w/ pivoting + constexpr log)
// ---------------------------------------------------------------------------
struct TPSConst { float li[NCOEF][NCP]; };

constexpr double cfabs(double x) { return x < 0.0 ? -x : x; }

constexpr double clog(double x) {
    int e = 0;
    while (x >= 1.4142135623730951) { x *= 0.5; e++; }
    while (x <  0.7071067811865476) { x *= 2.0; e--; }
    double t = (x - 1.0) / (x + 1.0), t2 = t * t, p = t, s = 0.0;
    for (int k = 0; k < 27; k++) { s += p / (double)(2 * k + 1); p *= t2; }
    return 2.0 * s + (double)e * 0.6931471805599453094172321214581766;
}

constexpr TPSConst make_tps() {
    TPSConst r{};
    const double ax[5] = {-1.0, -0.5, 0.0, 0.5, 1.0};
    double PX[NCP] = {}, PY[NCP] = {};
    for (int i = 0; i < 5; i++)
        for (int j = 0; j < 5; j++) { PX[i*5+j] = ax[i]; PY[i*5+j] = ax[j]; }

    double a[28][56] = {};
    for (int i = 0; i < 25; i++)
        for (int j = 0; j < 25; j++) {
            if (i != j) {
                double dx = PX[i]-PX[j], dy = PY[i]-PY[j];
                double d2 = dx*dx + dy*dy;
                a[i][j] = d2 * clog(d2);
            }
        }
    for (int i = 0; i < 25; i++) {
        a[i][25] = 1.0; a[i][26] = PX[i]; a[i][27] = PY[i];
        a[25][i] = 1.0; a[26][i] = PX[i]; a[27][i] = PY[i];
    }
    for (int i = 0; i < 28; i++) a[i][28+i] = 1.0;

    for (int k = 0; k < 28; k++) {
        int piv = k; double best = cfabs(a[k][k]);
        for (int i = k+1; i < 28; i++) {
            double v = cfabs(a[i][k]);
            if (v > best) { best = v; piv = i; }
        }
        if (piv != k)
            for (int j = 0; j < 56; j++) {
                double t = a[k][j]; a[k][j] = a[piv][j]; a[piv][j] = t;
            }
        double inv = 1.0 / a[k][k];
        for (int j = 0; j < 56; j++) a[k][j] *= inv;
        for (int i = 0; i < 28; i++) {
            if (i == k) continue;
            double f = a[i][k];
            if (f != 0.0)
                for (int j = 0; j < 56; j++) a[i][j] -= f * a[k][j];
        }
    }
    for (int n = 0; n < NCOEF; n++)
        for (int m = 0; m < NCP; m++)
            r.li[n][m] = (float)a[n][28 + m];
    return r;
}

// Transposed + lane-duplicated Li (staged to smem per block).
struct alignas(16) TPSLi2 { float2 v[NCP][4][8]; };

constexpr TPSLi2 make_li2() {
    TPSLi2 r{};
    TPSConst t = make_tps();
    for (int m = 0; m < NCP; m++)
        for (int part = 0; part < 4; part++)
            for (int j = 0; j < 7; j++) {
                float v = t.li[part * 7 + j][m];
                r.v[m][part][j] = float2{v, v};
            }
    return r;
}

__device__ const TPSLi2 g_li2 = make_li2();

// ---------------------------------------------------------------------------
// Packed f32x2 helpers
// ---------------------------------------------------------------------------
__device__ __forceinline__ unsigned long long pack2(float lo, float hi) {
    unsigned long long r;
    asm("mov.b64 %0, {%1, %2};" : "=l"(r) : "f"(lo), "f"(hi));
    return r;
}
__device__ __forceinline__ unsigned long long fma2(unsigned long long a,
                                                   unsigned long long b,
                                                   unsigned long long c) {
    unsigned long long d;
    asm("fma.rn.f32x2 %0, %1, %2, %3;" : "=l"(d) : "l"(a), "l"(b), "l"(c));
    return d;
}

// ---------------------------------------------------------------------------
// Fused kernel. grid (192, 4), block 128, 5 blocks/SM.
// Each thread: 2 adjacent-w pixels x 16 batches.
// ---------------------------------------------------------------------------
__global__ __launch_bounds__(128, 5) void tps_fused_kernel(
    const float* __restrict__ theta, float2* __restrict__ out) {

    __shared__ __align__(16) float  s_theta[NBQ * 2 * NCP];   // 3.2 KB
    __shared__ __align__(16) float2 s_li[NCP * 4 * 8];        // 6.4 KB
    __shared__ __align__(16) float4 s_coef[NBQ * NCOEF];      // 7.2 KB (cx,cx,cy,cy)

    const int tid   = threadIdx.x;
    const int qtr   = blockIdx.y;          // which 16-batch quarter
    const int bbase = qtr * NBQ;

    // ---- Stage theta (200 float4) + Li (400 float4) coalesced ----
    {
        const float4* tsrc = (const float4*)(theta + bbase * 2 * NCP);
        const float4* lsrc = (const float4*)&g_li2;
        float4* tdst = (float4*)s_theta;
        float4* ldst = (float4*)s_li;
        for (int i = tid; i < 400; i += 128) {
            if (i < 200) tdst[i] = tsrc[i];
            ldst[i] = lsrc[i];
        }
    }
    __syncthreads();

    // ---- Phase A: coef solve (64 active threads), immediate writeback ----
    if (tid < 64) {
        const int b    = tid & 15;         // batch within quarter
        const int part = tid >> 4;         // coef quarter 0..3
        unsigned long long acc[7];
#pragma unroll
        for (int j = 0; j < 7; j++) acc[j] = 0ull;
        const float* trow = s_theta + b * (2 * NCP);
#pragma unroll
        for (int m = 0; m < NCP; m++) {
            const unsigned long long q2 =
                pack2(trow[m] + cpx(m), trow[NCP + m] + cpy(m));
            const unsigned long long* lrow =
                (const unsigned long long*)(s_li + (m * 4 + part) * 8);
#pragma unroll
            for (int j = 0; j < 7; j++)
                acc[j] = fma2(lrow[j], q2, acc[j]);   // LDS broadcast
        }
#pragma unroll
        for (int j = 0; j < 7; j++) {
            float x, y;
            asm("mov.b64 {%0, %1}, %2;" : "=f"(x), "=f"(y) : "l"(acc[j]));
            s_coef[b * NCOEF + part * 7 + j] = make_float4(x, x, y, y);
        }
    }

    // ---- U vectors for TWO adjacent-w pixels, packed (u_px0, u_px1) ----
    const int pid0 = blockIdx.x * 256 + tid * 2;
    const int h  = pid0 / OUT_W;
    const int w0 = pid0 - h * OUT_W;

    const float gy  = (h == OUT_H - 1) ? 1.0f
                      : (float)(-1.0 + (double)h * (2.0 / (double)(OUT_H - 1)));
    const float gx0 = (float)(-1.0 + (double)w0 * (2.0 / (double)(OUT_W - 1)));
    const float gx1 = (w0 + 1 == OUT_W - 1) ? 1.0f
                      : (float)(-1.0 + (double)(w0 + 1) * (2.0 / (double)(OUT_W - 1)));

    unsigned long long U[NCOEF];
#pragma unroll
    for (int n = 0; n < NCP; n++) {
        const float dy  = gy - cpy(n);
        const float dy2 = dy * dy;
        const float dx0 = gx0 - cpx(n);
        const float dx1 = gx1 - cpx(n);
        const float d20 = dx0 * dx0 + dy2;
        const float d21 = dx1 * dx1 + dy2;
        const float u0 = (d20 == 0.0f) ? 0.0f : d20 * __logf(d20);
        const float u1 = (d21 == 0.0f) ? 0.0f : d21 * __logf(d21);
        U[n] = pack2(u0, u1);
    }
    U[25] = pack2(1.0f, 1.0f);
    U[26] = pack2(gx0, gx1);
    U[27] = pack2(gy, gy);

    __syncthreads();   // coefs visible

    // ---- Phase B: 16 batches, 2 per iter (4 chains) ----
    char* obase = (char*)out + ((size_t)(bbase * OUT_H + h) * OUT_W + w0) * 8;
    const size_t ostride = (size_t)OUT_H * OUT_W * 8;
    for (int bl = 0; bl < NBQ; bl += 2) {
        const ulonglong2* c0 = (const ulonglong2*)(s_coef + (bl)     * NCOEF);
        const ulonglong2* c1 = (const ulonglong2*)(s_coef + (bl + 1) * NCOEF);
        unsigned long long ax0 = 0ull, ay0 = 0ull, ax1 = 0ull, ay1 = 0ull;
#pragma unroll
        for (int k = 0; k < NCOEF; k++) {
            const ulonglong2 p0 = c0[k];   // ((cx,cx),(cy,cy)) batch bl
            const ulonglong2 p1 = c1[k];   // batch bl+1
            ax0 = fma2(U[k], p0.x, ax0);
            ay0 = fma2(U[k], p0.y, ay0);
            ax1 = fma2(U[k], p1.x, ax1);
            ay1 = fma2(U[k], p1.y, ay1);
        }
        // ax=(x0,x1), ay=(y0,y1) -> interleave to (x0,y0,x1,y1), one STG.128 each
        float x00, x01, y00, y01, x10, x11, y10, y11;
        asm("mov.b64 {%0, %1}, %2;" : "=f"(x00), "=f"(x01) : "l"(ax0));
        asm("mov.b64 {%0, %1}, %2;" : "=f"(y00), "=f"(y01) : "l"(ay0));
        asm("mov.b64 {%0, %1}, %2;" : "=f"(x10), "=f"(x11) : "l"(ax1));
        asm("mov.b64 {%0, %1}, %2;" : "=f"(y10), "=f"(y11) : "l"(ay1));
        *(float4*)(obase)           = make_float4(x00, y00, x01, y01);
        *(float4*)(obase + ostride) = make_float4(x10, y10, x11, y11);
        obase += 2 * ostride;
    }
}

// ---------------------------------------------------------------------------
extern "C" void kernel_launch(void* const* d_in, const int* in_sizes, int n_in,
                              void* d_out, int out_size) {
    const float* theta = (const float*)d_in[0];
    (void)in_sizes; (void)n_in; (void)out_size;

    dim3 grid(OUT_H * OUT_W / 256, 4);
    tps_fused_kernel<<<grid, 128>>>(theta, (float2*)d_out);
}

// round 10
// speedup vs baseline: 1.2581x; 1.2581x over previous
#include <cuda_runtime.h>

// TpsGridGen: theta (64, 50) -> grid (64, 256, 192, 2) fp32
// R10: 3 pixels/thread (warp-strided), 32 batches/block.
//   Coefs non-duplicated (float2 x,y): each LDS.128 = 2 coefs feeds 6 FFMA2
//   (3 px). U duplicated (u,u) per pixel: 168 regs -> launch_bounds(128,2).
//   Instr/work = 0.76x of R8; LSU wavefronts/work = 0.67x.

#define OUT_H 256
#define OUT_W 192
#define NCP   25
#define NCOEF 28   // 25 RBF + [1, gx, gy] affine

__host__ __device__ constexpr float cpx(int n) { return 0.5f * (float)(n / 5) - 1.0f; }
__host__ __device__ constexpr float cpy(int n) { return 0.5f * (float)(n % 5) - 1.0f; }

// ---------------------------------------------------------------------------
// Compile-time inv(L) (constexpr fp64 Gauss-Jordan w/ pivoting + constexpr log)
// ---------------------------------------------------------------------------
struct TPSConst { float li[NCOEF][NCP]; };

constexpr double cfabs(double x) { return x < 0.0 ? -x : x; }

constexpr double clog(double x) {
    int e = 0;
    while (x >= 1.4142135623730951) { x *= 0.5; e++; }
    while (x <  0.7071067811865476) { x *= 2.0; e--; }
    double t = (x - 1.0) / (x + 1.0), t2 = t * t, p = t, s = 0.0;
    for (int k = 0; k < 27; k++) { s += p / (double)(2 * k + 1); p *= t2; }
    return 2.0 * s + (double)e * 0.6931471805599453094172321214581766;
}

constexpr TPSConst make_tps() {
    TPSConst r{};
    const double ax[5] = {-1.0, -0.5, 0.0, 0.5, 1.0};
    double PX[NCP] = {}, PY[NCP] = {};
    for (int i = 0; i < 5; i++)
        for (int j = 0; j < 5; j++) { PX[i*5+j] = ax[i]; PY[i*5+j] = ax[j]; }

    double a[28][56] = {};
    for (int i = 0; i < 25; i++)
        for (int j = 0; j < 25; j++) {
            if (i != j) {
                double dx = PX[i]-PX[j], dy = PY[i]-PY[j];
                double d2 = dx*dx + dy*dy;
                a[i][j] = d2 * clog(d2);
            }
        }
    for (int i = 0; i < 25; i++) {
        a[i][25] = 1.0; a[i][26] = PX[i]; a[i][27] = PY[i];
        a[25][i] = 1.0; a[26][i] = PX[i]; a[27][i] = PY[i];
    }
    for (int i = 0; i < 28; i++) a[i][28+i] = 1.0;

    for (int k = 0; k < 28; k++) {
        int piv = k; double best = cfabs(a[k][k]);
        for (int i = k+1; i < 28; i++) {
            double v = cfabs(a[i][k]);
            if (v > best) { best = v; piv = i; }
        }
        if (piv != k)
            for (int j = 0; j < 56; j++) {
                double t = a[k][j]; a[k][j] = a[piv][j]; a[piv][j] = t;
            }
        double inv = 1.0 / a[k][k];
        for (int j = 0; j < 56; j++) a[k][j] *= inv;
        for (int i = 0; i < 28; i++) {
            if (i == k) continue;
            double f = a[i][k];
            if (f != 0.0)
                for (int j = 0; j < 56; j++) a[i][j] -= f * a[k][j];
        }
    }
    for (int n = 0; n < NCOEF; n++)
        for (int m = 0; m < NCP; m++)
            r.li[n][m] = (float)a[n][28 + m];
    return r;
}

// Transposed + lane-duplicated Li (staged to smem per block, for phase A).
struct alignas(16) TPSLi2 { float2 v[NCP][4][8]; };

constexpr TPSLi2 make_li2() {
    TPSLi2 r{};
    TPSConst t = make_tps();
    for (int m = 0; m < NCP; m++)
        for (int part = 0; part < 4; part++)
            for (int j = 0; j < 7; j++) {
                float v = t.li[part * 7 + j][m];
                r.v[m][part][j] = float2{v, v};
            }
    return r;
}

__device__ const TPSLi2 g_li2 = make_li2();

// ---------------------------------------------------------------------------
// Packed f32x2 helpers
// ---------------------------------------------------------------------------
__device__ __forceinline__ unsigned long long pack2(float lo, float hi) {
    unsigned long long r;
    asm("mov.b64 %0, {%1, %2};" : "=l"(r) : "f"(lo), "f"(hi));
    return r;
}
__device__ __forceinline__ unsigned long long fma2(unsigned long long a,
                                                   unsigned long long b,
                                                   unsigned long long c) {
    unsigned long long d;
    asm("fma.rn.f32x2 %0, %1, %2, %3;" : "=l"(d) : "l"(a), "l"(b), "l"(c));
    return d;
}

__device__ __forceinline__ float gridx(int w) {
    return (w == OUT_W - 1) ? 1.0f
           : (float)(-1.0 + (double)w * (2.0 / (double)(OUT_W - 1)));
}

// ---------------------------------------------------------------------------
// Fused kernel. grid (128, 2), block 128. Each thread: 3 warp-strided pixels
// (lane, lane+32, lane+64 within a 96-px row chunk) x 32 batches.
// ---------------------------------------------------------------------------
__global__ __launch_bounds__(128, 2) void tps_fused_kernel(
    const float* __restrict__ theta, float2* __restrict__ out) {

    __shared__ __align__(16) float  s_theta[32 * 2 * NCP];   // 6.4 KB
    __shared__ __align__(16) float2 s_li[NCP * 4 * 8];       // 6.4 KB
    __shared__ __align__(16) float2 s_coef[32 * NCOEF];      // 7.2 KB (x,y)

    const int tid   = threadIdx.x;
    const int wid   = tid >> 5;
    const int lid   = tid & 31;
    const int half  = blockIdx.y;
    const int bbase = half * 32;

    // ---- Stage theta (400 float4) + Li (400 float4) coalesced ----
    {
        const float4* tsrc = (const float4*)(theta + half * 32 * 2 * NCP);
        const float4* lsrc = (const float4*)&g_li2;
        float4* tdst = (float4*)s_theta;
        float4* ldst = (float4*)s_li;
        for (int i = tid; i < 400; i += 128) {
            tdst[i] = tsrc[i];
            ldst[i] = lsrc[i];
        }
    }
    __syncthreads();

    // ---- Phase A: coef solve (lane = batch, warp = coef quarter) ----
    {
        const int b    = tid & 31;
        const int part = tid >> 5;
        unsigned long long acc[7];
#pragma unroll
        for (int j = 0; j < 7; j++) acc[j] = 0ull;
        const float* trow = s_theta + b * (2 * NCP);
#pragma unroll
        for (int m = 0; m < NCP; m++) {
            const unsigned long long q2 =
                pack2(trow[m] + cpx(m), trow[NCP + m] + cpy(m));
            const unsigned long long* lrow =
                (const unsigned long long*)(s_li + (m * 4 + part) * 8);
#pragma unroll
            for (int j = 0; j < 7; j++)
                acc[j] = fma2(lrow[j], q2, acc[j]);   // LDS broadcast
        }
        unsigned long long* dst =
            (unsigned long long*)(s_coef + b * NCOEF + part * 7);
#pragma unroll
        for (int j = 0; j < 7; j++) dst[j] = acc[j];
    }

    // ---- U for 3 warp-strided pixels (same row; dup (u,u) per pixel) ----
    const int wbase = blockIdx.x * 384 + wid * 96;  // 96 px chunk, within one row
    const int px0 = wbase + lid;                    // +0, +32, +64
    const int h  = px0 / OUT_W;
    const int w0 = px0 - h * OUT_W;

    const float gy  = (h == OUT_H - 1) ? 1.0f
                      : (float)(-1.0 + (double)h * (2.0 / (double)(OUT_H - 1)));
    const float gx0 = gridx(w0);
    const float gx1 = gridx(w0 + 32);
    const float gx2 = gridx(w0 + 64);

    unsigned long long U0[NCOEF], U1[NCOEF], U2[NCOEF];
#pragma unroll
    for (int n = 0; n < NCP; n++) {
        const float dy  = gy - cpy(n);
        const float dy2 = dy * dy;
        const float dx0 = gx0 - cpx(n);
        const float dx1 = gx1 - cpx(n);
        const float dx2 = gx2 - cpx(n);
        const float d20 = dx0 * dx0 + dy2;
        const float d21 = dx1 * dx1 + dy2;
        const float d22 = dx2 * dx2 + dy2;
        const float u0 = (d20 == 0.0f) ? 0.0f : d20 * __logf(d20);
        const float u1 = (d21 == 0.0f) ? 0.0f : d21 * __logf(d21);
        const float u2 = (d22 == 0.0f) ? 0.0f : d22 * __logf(d22);
        U0[n] = pack2(u0, u0);
        U1[n] = pack2(u1, u1);
        U2[n] = pack2(u2, u2);
    }
    U0[25] = pack2(1.0f, 1.0f);  U1[25] = U0[25];          U2[25] = U0[25];
    U0[26] = pack2(gx0, gx0);    U1[26] = pack2(gx1, gx1); U2[26] = pack2(gx2, gx2);
    U0[27] = pack2(gy, gy);      U1[27] = U0[27];          U2[27] = U0[27];

    __syncthreads();   // coefs visible

    // ---- Phase B: 32 batches, 2 per iter; 6 chains; 1 LDS.128 : 6 FMA2 ----
    char* obase = (char*)out + ((size_t)(bbase * OUT_H) * OUT_W + px0) * 8;
    const size_t ostride = (size_t)OUT_H * OUT_W * 8;
    for (int bl = 0; bl < 32; bl += 2) {
        const ulonglong2* c0 = (const ulonglong2*)(s_coef + (bl)     * NCOEF);
        const ulonglong2* c1 = (const ulonglong2*)(s_coef + (bl + 1) * NCOEF);
        unsigned long long a00 = 0ull, a01 = 0ull, a02 = 0ull;
        unsigned long long a10 = 0ull, a11 = 0ull, a12 = 0ull;
#pragma unroll
        for (int q = 0; q < NCOEF / 2; q++) {
            const ulonglong2 p0 = c0[q];   // (x,y) of coefs 2q, 2q+1, batch bl
            const ulonglong2 p1 = c1[q];
            a00 = fma2(U0[2*q], p0.x, a00); a00 = fma2(U0[2*q+1], p0.y, a00);
            a01 = fma2(U1[2*q], p0.x, a01); a01 = fma2(U1[2*q+1], p0.y, a01);
            a02 = fma2(U2[2*q], p0.x, a02); a02 = fma2(U2[2*q+1], p0.y, a02);
            a10 = fma2(U0[2*q], p1.x, a10); a10 = fma2(U0[2*q+1], p1.y, a10);
            a11 = fma2(U1[2*q], p1.x, a11); a11 = fma2(U1[2*q+1], p1.y, a11);
            a12 = fma2(U2[2*q], p1.x, a12); a12 = fma2(U2[2*q+1], p1.y, a12);
        }
        // coalesced STG.64: lanes contiguous; pixels +32/+64 = +256B/+512B
        *(unsigned long long*)(obase)                 = a00;
        *(unsigned long long*)(obase + 256)           = a01;
        *(unsigned long long*)(obase + 512)           = a02;
        *(unsigned long long*)(obase + ostride)       = a10;
        *(unsigned long long*)(obase + ostride + 256) = a11;
        *(unsigned long long*)(obase + ostride + 512) = a12;
        obase += 2 * ostride;
    }
}

// ---------------------------------------------------------------------------
extern "C" void kernel_launch(void* const* d_in, const int* in_sizes, int n_in,
                              void* d_out, int out_size) {
    const float* theta = (const float*)d_in[0];
    (void)in_sizes; (void)n_in; (void)out_size;

    dim3 grid(OUT_H * OUT_W / 384, 2);   // (128, 2)
    tps_fused_kernel<<<grid, 128>>>(theta, (float2*)d_out);
}